// round 8
// baseline (speedup 1.0000x reference)
#include <cuda_runtime.h>

// EMA y_t = (1-w)*y_{t-1} + w*x_t — decoupled-lookback scan, v6.
// R5 post-mortem: scalar STG.32 (5cyc issue) made all prior versions
// LSU-issue-bound (~218 LSU-cyc per 8KB > ~6150 DRAM-cyc per 256KB/SM).
// v6: thread = 2 adjacent channels, all hot traffic as 64-bit LDG/STG
// (153 LSU-cyc per 8KB -> DRAM-bound), packed f32x2 math, register stash
// of zero-entry partials, per-thread lookback, batch-fast grid.

typedef unsigned long long u64;

#define TT   8192
#define CC   256
#define LL   16
#define NCH  (TT / LL)   // 512 chunks per batch row
#define MAXB 16
#define NTH  128         // threads/block: 128 channel-pairs

// carry word per (b,chunk,channel): high32 = flag (0 none/1 agg/2 prefix),
// low32 = float payload. Zeroed each launch.
__device__ u64 g_carry[MAXB * NCH * CC];

// packed f32x2 helpers (plain asm: pure, schedulable)
__device__ __forceinline__ u64 f2fma(u64 a, u64 b, u64 c) {
    u64 d; asm("fma.rn.f32x2 %0, %1, %2, %3;" : "=l"(d) : "l"(a), "l"(b), "l"(c)); return d;
}
__device__ __forceinline__ u64 f2mul(u64 a, u64 b) {
    u64 d; asm("mul.rn.f32x2 %0, %1, %2;" : "=l"(d) : "l"(a), "l"(b)); return d;
}
__device__ __forceinline__ u64 pk(float lo, float hi) {
    u64 d; asm("mov.b64 %0, {%1, %2};" : "=l"(d) : "f"(lo), "f"(hi)); return d;
}

__global__ void ema_clear_kernel(int n2) {
    int i = blockIdx.x * blockDim.x + threadIdx.x;
    if (i < n2) ((ulonglong2*)g_carry)[i] = make_ulonglong2(0ULL, 0ULL);
}

__global__ __launch_bounds__(NTH, 8) void ema_scan_kernel(
    const float* __restrict__ x,
    const float* __restrict__ y0,
    const float* __restrict__ smooth,
    float* __restrict__ out,
    int B)
{
    // batch-fast grid: predecessor (k-1,b) is exactly B bids lower.
    const int b = blockIdx.x % B;
    const int k = blockIdx.x / B;
    const int ch0 = threadIdx.x * 2;       // this thread's channel pair

    const float2 sm = *(const float2*)(smooth + ch0);
    const float w0 = fminf(fmaxf(sm.x, 0.f), 1.f);
    const float w1 = fminf(fmaxf(sm.y, 0.f), 1.f);
    const u64 w01 = pk(w0, w1);
    const u64 a01 = pk(1.f - w0, 1.f - w1);
    const float a0 = 1.f - w0, a1 = 1.f - w1;

    // AL = a^16 (packed, 4 squarings)
    u64 t = f2mul(a01, a01); t = f2mul(t, t); t = f2mul(t, t);
    const u64 AL01 = f2mul(t, t);
    float t0 = a0 * a0; t0 *= t0; t0 *= t0; const float AL0 = t0 * t0;
    float t1 = a1 * a1; t1 *= t1; t1 *= t1; const float AL1 = t1 * t1;

    // ---- Phase A: single 64-bit read of the chunk; stash zero-entry
    //      partials ys[i] = sum_{j<=i} a^(i-j) w x_j (packed pair). ----
    const size_t base = (size_t)(b * TT + k * LL) * CC + ch0;
    const u64* xp = (const u64*)(x + base);
    u64 ys[LL];
    u64 e01 = 0ULL;
#pragma unroll
    for (int i = 0; i < LL; i++) {
        u64 xv = __ldcs(xp + i * (CC / 2));
        e01 = f2fma(a01, e01, f2mul(w01, xv));
        ys[i] = e01;
    }

    volatile u64* cb = g_carry + (size_t)(b * NCH) * CC + ch0;
    u64* cp = (u64*)(g_carry + (size_t)(b * NCH + k) * CC + ch0);

    // publish aggregates (flag=1): one 16B store, each 8B word self-contained
    asm volatile("st.global.v2.u64 [%0], {%1, %2};" :: "l"(cp),
        "l"((1ULL << 32) | (u64)(unsigned)e01),
        "l"((1ULL << 32) | (e01 >> 32)) : "memory");

    // ---- Lookback: fold predecessor aggregates, short-circuit on prefixes.
    //      Per-channel flags (a v2 store pair could in principle tear). ----
    float acc0, acc1;
    if (k == 0) {
        const float2 yv = *(const float2*)(y0 + b * CC + ch0);
        acc0 = yv.x; acc1 = yv.y;
    } else {
        acc0 = 0.f; acc1 = 0.f;
        float m0 = 1.f, m1 = 1.f;
        bool dn0 = false, dn1 = false;
        int j = k - 1;
        for (;;) {
            const int g = (j + 1 < 4) ? (j + 1) : 4;
            u64 v0[4], v1[4];
            bool ok;
            do {  // batched spin: up to 8 independent volatile 8B reads
                ok = true;
#pragma unroll
                for (int u = 0; u < 4; u++) {
                    if (u < g) {
                        v0[u] = cb[(size_t)(j - u) * CC];
                        v1[u] = cb[(size_t)(j - u) * CC + 1];
                        if (!(v0[u] >> 32) || !(v1[u] >> 32)) ok = false;
                    }
                }
            } while (!ok);
#pragma unroll
            for (int u = 0; u < 4; u++) {
                if (u < g) {
                    if (!dn0) {
                        acc0 = fmaf(m0, __uint_as_float((unsigned)v0[u]), acc0);
                        if ((unsigned)(v0[u] >> 32) == 2u) dn0 = true; else m0 *= AL0;
                    }
                    if (!dn1) {
                        acc1 = fmaf(m1, __uint_as_float((unsigned)v1[u]), acc1);
                        if ((unsigned)(v1[u] >> 32) == 2u) dn1 = true; else m1 *= AL1;
                    }
                }
            }
            j -= g;
            if (dn0 && dn1) break;
            if (j < 0) {   // folded every aggregate; add the initial state
                const float2 yv = *(const float2*)(y0 + b * CC + ch0);
                if (!dn0) acc0 = fmaf(m0, yv.x, acc0);
                if (!dn1) acc1 = fmaf(m1, yv.y, acc1);
                break;
            }
        }
    }

    const u64 acc01 = pk(acc0, acc1);

    // publish inclusive prefix (flag=2) so downstream chunks short-circuit
    const u64 P01 = f2fma(AL01, acc01, e01);
    asm volatile("st.global.v2.u64 [%0], {%1, %2};" :: "l"(cp),
        "l"((2ULL << 32) | (u64)(unsigned)P01),
        "l"((2ULL << 32) | (P01 >> 32)) : "memory");

    // ---- Phase C: dependency-free fixup, 64-bit streaming stores ----
    u64* op = (u64*)(out + base);
    u64 pw01 = a01;   // a^(i+1), packed
#pragma unroll
    for (int i = 0; i < LL; i++) {
        __stcs(op + i * (CC / 2), f2fma(pw01, acc01, ys[i]));
        pw01 = f2mul(pw01, a01);
    }
}

extern "C" void kernel_launch(void* const* d_in, const int* in_sizes, int n_in,
                              void* d_out, int out_size) {
    const float* x      = (const float*)d_in[0];  // [B, T, C]
    const float* y0     = (const float*)d_in[1];  // [B, C]
    const float* smooth = (const float*)d_in[2];  // [C]
    float* out          = (float*)d_out;

    const int B = in_sizes[0] / (TT * CC);

    const int n2 = (B * NCH * CC) / 2;            // ulonglong2 words
    ema_clear_kernel<<<(n2 + 255) / 256, 256>>>(n2);
    ema_scan_kernel<<<B * NCH, NTH>>>(x, y0, smooth, out, B);
}